// round 12
// baseline (speedup 1.0000x reference)
#include <cuda_runtime.h>
#include <cuda_fp16.h>
#include <cstdint>

#define NNODES   8192
#define EMAX     131072
#define ESEL     65536
#define HID      768
#define MSG      249
#define MSGP     256
#define LN_EPS   1e-5f

// ============================ PTX helpers (baseline, sm_80+) ============================
__device__ __forceinline__ uint32_t smem_to_u32(const void* p) {
    uint32_t a;
    asm("{ .reg .u64 t; cvta.to.shared.u64 t, %1; cvt.u32.u64 %0, t; }" : "=r"(a) : "l"(p));
    return a;
}
__device__ __forceinline__ void cp16(uint32_t s, const void* g) {
    asm volatile("cp.async.cg.shared.global [%0], [%1], 16;" :: "r"(s), "l"(g));
}
#define CP_COMMIT  asm volatile("cp.async.commit_group;" ::: "memory")
#define CP_WAIT2   asm volatile("cp.async.wait_group 2;" ::: "memory")

__device__ __forceinline__ void ldsm_x4(uint32_t* r, uint32_t addr) {
    asm volatile("ldmatrix.sync.aligned.m8n8.x4.shared.b16 {%0,%1,%2,%3}, [%4];"
        : "=r"(r[0]), "=r"(r[1]), "=r"(r[2]), "=r"(r[3]) : "r"(addr));
}
__device__ __forceinline__ void ldsm_x2(uint32_t* r, uint32_t addr) {
    asm volatile("ldmatrix.sync.aligned.m8n8.x2.shared.b16 {%0,%1}, [%2];"
        : "=r"(r[0]), "=r"(r[1]) : "r"(addr));
}
__device__ __forceinline__ void mma16816(float* d, const uint32_t* a, const uint32_t* b) {
    asm volatile("mma.sync.aligned.m16n8k16.row.col.f32.f16.f16.f32 "
        "{%0,%1,%2,%3}, {%4,%5,%6,%7}, {%8,%9}, {%0,%1,%2,%3};"
        : "+f"(d[0]), "+f"(d[1]), "+f"(d[2]), "+f"(d[3])
        : "r"(a[0]), "r"(a[1]), "r"(a[2]), "r"(a[3]), "r"(b[0]), "r"(b[1]));
}
__device__ __forceinline__ uint32_t pack2(float a, float b) {
    return (uint32_t)__half_as_ushort(__float2half_rn(a))
         | ((uint32_t)__half_as_ushort(__float2half_rn(b)) << 16);
}

// ============================ scratch ============================
__device__ __half g_h1[(size_t)ESEL * HID];
__device__ __half g_h2[(size_t)ESEL * HID];
__device__ __half g_w2t[HID * HID];
__device__ __half g_w3t[MSGP * HID];
__device__ float g_b3p[MSGP];
__device__ float g_sea[ESEL * 6];
__device__ int   g_ssrc[ESEL];
__device__ int   g_sdst[ESEL];
__device__ float g_agg[NNODES * 3];
__device__ int   g_bcnt[1024];
__device__ int   g_boff[1024];
__device__ int   g_pidx[83];

__device__ __forceinline__ float leaky(float v) { return v > 0.f ? v : 0.01f * v; }

// ============================ edge compaction (src < dst) ============================
__global__ void k_count(const int* __restrict__ src, const int* __restrict__ dst, int E) {
    int e = blockIdx.x * blockDim.x + threadIdx.x;
    int pred = (e < E) && (src[e] < dst[e]);
    unsigned bal = __ballot_sync(0xffffffffu, pred);
    __shared__ int wc[32];
    int wid = threadIdx.x >> 5, lane = threadIdx.x & 31;
    if (lane == 0) wc[wid] = __popc(bal);
    __syncthreads();
    if (threadIdx.x == 0) {
        int nmw = blockDim.x >> 5, s = 0;
        for (int i = 0; i < nmw; i++) s += wc[i];
        g_bcnt[blockIdx.x] = s;
    }
}
__global__ void k_scan(int nb) {
    __shared__ int s[1024];
    int t = threadIdx.x;
    if (t < nb) s[t] = g_bcnt[t];
    __syncthreads();
    if (t == 0) { int acc = 0; for (int i = 0; i < nb; i++) { int v = s[i]; s[i] = acc; acc += v; } }
    __syncthreads();
    if (t < nb) g_boff[t] = s[t];
}
__global__ void k_scatter(const int* __restrict__ src, const int* __restrict__ dst,
                          const float* __restrict__ ea, int E) {
    int e = blockIdx.x * blockDim.x + threadIdx.x;
    int pred = (e < E) && (src[e] < dst[e]);
    unsigned bal = __ballot_sync(0xffffffffu, pred);
    __shared__ int wc[32], ws[32];
    int wid = threadIdx.x >> 5, lane = threadIdx.x & 31;
    if (lane == 0) wc[wid] = __popc(bal);
    __syncthreads();
    if (threadIdx.x == 0) {
        int nmw = blockDim.x >> 5, acc = 0;
        for (int i = 0; i < nmw; i++) { ws[i] = acc; acc += wc[i]; }
    }
    __syncthreads();
    if (pred) {
        int idx = g_boff[blockIdx.x] + ws[wid] + __popc(bal & ((1u << lane) - 1u));
        g_ssrc[idx] = src[e];
        g_sdst[idx] = dst[e];
        #pragma unroll
        for (int k = 0; k < 6; k++) g_sea[idx * 6 + k] = ea[(size_t)e * 6 + k];
    }
}

// ============================ prep: coalesced transposes + misc ============================
__global__ __launch_bounds__(256)
void k_tw2(const float* __restrict__ W2) {
    __shared__ float tile[32][33];
    int bx = blockIdx.x * 32, by = blockIdx.y * 32;
    int tx = threadIdx.x & 31, ty = threadIdx.x >> 5;
    #pragma unroll
    for (int i = 0; i < 4; i++) {
        int k = by + ty + i * 8;
        tile[ty + i * 8][tx] = W2[(size_t)k * HID + bx + tx];
    }
    __syncthreads();
    #pragma unroll
    for (int i = 0; i < 4; i++) {
        int n = bx + ty + i * 8;
        g_w2t[(size_t)n * HID + by + tx] = __float2half_rn(tile[tx][ty + i * 8]);
    }
}
__global__ __launch_bounds__(256)
void k_tw3(const float* __restrict__ W3) {
    __shared__ float tile[32][33];
    int bx = blockIdx.x * 32, by = blockIdx.y * 32;
    int tx = threadIdx.x & 31, ty = threadIdx.x >> 5;
    #pragma unroll
    for (int i = 0; i < 4; i++) {
        int k = by + ty + i * 8;
        int n = bx + tx;
        tile[ty + i * 8][tx] = (n < MSG) ? W3[(size_t)k * MSG + n] : 0.f;
    }
    __syncthreads();
    #pragma unroll
    for (int i = 0; i < 4; i++) {
        int n = bx + ty + i * 8;
        g_w3t[(size_t)n * HID + by + tx] = __float2half_rn(tile[tx][ty + i * 8]);
    }
}
__global__ void k_misc(const float* __restrict__ b3) {
    int idx = blockIdx.x * blockDim.x + threadIdx.x;
    if (idx < MSGP) g_b3p[idx] = (idx < MSG) ? b3[idx] : 0.f;
    if (idx < NNODES * 3) g_agg[idx] = 0.f;
    if (idx == 0) {
        int p = 0;
        for (int a = 0; a < 6; a++) g_pidx[p++] = a | (6 << 8) | (6 << 16);
        for (int a = 0; a < 6; a++)
            for (int b = a; b < 6; b++) g_pidx[p++] = a | (b << 8) | (6 << 16);
        for (int a = 0; a < 6; a++)
            for (int b = a; b < 6; b++)
                for (int c = b; c < 6; c++) g_pidx[p++] = a | (b << 8) | (c << 16);
    }
}

// ============================ layer1 vectorized: 8 edges/block, 16B stores ============================
__global__ __launch_bounds__(256)
void k_layer1v(const float* __restrict__ W1, const float* __restrict__ b1) {
    __shared__ float sW1[6 * 768];
    __shared__ float sb1[768];
    __shared__ float sea[8][6];
    int t = threadIdx.x;
    int e0 = blockIdx.x * 8;
    for (int i = t; i < (6 * 768) / 4; i += 256)
        ((float4*)sW1)[i] = ((const float4*)W1)[i];
    for (int i = t; i < 768 / 4; i += 256)
        ((float4*)sb1)[i] = ((const float4*)b1)[i];
    if (t < 48) sea[t / 6][t % 6] = g_sea[e0 * 6 + t];
    __syncthreads();

    #pragma unroll
    for (int it = 0; it < 3; it++) {
        int i = t + it * 256;
        int edge = i / 96;
        int grp  = i - edge * 96;
        int j0 = grp * 8;
        float e_[6];
        #pragma unroll
        for (int k = 0; k < 6; k++) e_[k] = sea[edge][k];
        float4 accA = *(const float4*)&sb1[j0];
        float4 accB = *(const float4*)&sb1[j0 + 4];
        #pragma unroll
        for (int k = 0; k < 6; k++) {
            float4 wA = *(const float4*)&sW1[k * 768 + j0];
            float4 wB = *(const float4*)&sW1[k * 768 + j0 + 4];
            accA.x += e_[k] * wA.x; accA.y += e_[k] * wA.y;
            accA.z += e_[k] * wA.z; accA.w += e_[k] * wA.w;
            accB.x += e_[k] * wB.x; accB.y += e_[k] * wB.y;
            accB.z += e_[k] * wB.z; accB.w += e_[k] * wB.w;
        }
        uint4 u;
        u.x = pack2(leaky(accA.x), leaky(accA.y));
        u.y = pack2(leaky(accA.z), leaky(accA.w));
        u.z = pack2(leaky(accB.x), leaky(accB.y));
        u.w = pack2(leaky(accB.z), leaky(accB.w));
        *(uint4*)(g_h1 + (size_t)(e0 + edge) * HID + j0) = u;
    }
}

// ============================ GEMM2: warp-MMA single-fp16 (R8-proven, exact) ============================
#define GSTAGE    16384
#define GEMM_SMEM (4 * GSTAGE + 128)

__global__ __launch_bounds__(256, 1)
void k_gemm_mma(const __half* __restrict__ A, const __half* __restrict__ B,
                const float* __restrict__ bias, __half* __restrict__ Ch,
                int K, int ldc)
{
    extern __shared__ char smem[];
    uint32_t sbase = (smem_to_u32(smem) + 127) & ~127u;
    int tid = threadIdx.x;
    int wid = tid >> 5, lane = tid & 31;
    int wm = wid >> 2, wn = wid & 3;
    int m0 = blockIdx.y * 128, n0 = blockIdx.x * 128;
    int S = K / 32;

    float acc[16][4];
    #pragma unroll
    for (int i = 0; i < 16; i++)
        #pragma unroll
        for (int j = 0; j < 4; j++) acc[i][j] = 0.f;

    auto load_stage = [&](int s, int b) {
        uint32_t bo = sbase + (uint32_t)b * GSTAGE;
        #pragma unroll
        for (int t = 0; t < 4; t++) {
            int i   = tid + t * 256;
            int mat = i >> 9;
            int rem = i & 511;
            int row = rem >> 2;
            int c   = rem & 3;
            const __half* g = (mat == 0 ? A + (size_t)(m0 + row) * K
                                        : B + (size_t)(n0 + row) * K);
            g += s * 32 + c * 8;
            uint32_t dstr = bo + (uint32_t)mat * 8192 + (uint32_t)row * 64
                          + (uint32_t)((c ^ (row & 3)) << 4);
            cp16(dstr, g);
        }
    };

    uint32_t aOff[4], aR3[4], bOff[4], bR3[4];
    {
        int arow_base = wm * 64 + ((lane >> 3) & 1) * 8 + (lane & 7);
        #pragma unroll
        for (int mt = 0; mt < 4; mt++) {
            int r = arow_base + mt * 16;
            aOff[mt] = (uint32_t)r * 64;
            aR3[mt] = (uint32_t)(r & 3);
        }
        int brow_base = wn * 32 + (lane & 7);
        #pragma unroll
        for (int nt = 0; nt < 4; nt++) {
            int r = brow_base + nt * 8;
            bOff[nt] = 8192u + (uint32_t)r * 64;
            bR3[nt] = (uint32_t)(r & 3);
        }
    }
    uint32_t aKadd = (uint32_t)(lane >> 4);
    uint32_t bKadd = (uint32_t)((lane >> 3) & 1);

    auto compute = [&](int b) {
        uint32_t base = sbase + (uint32_t)b * GSTAGE;
        #pragma unroll
        for (int ks = 0; ks < 2; ks++) {
            uint32_t af[4][4], bf[4][2];
            #pragma unroll
            for (int mt = 0; mt < 4; mt++) {
                uint32_t c = (uint32_t)(ks * 2) + aKadd;
                ldsm_x4(af[mt], base + aOff[mt] + ((c ^ aR3[mt]) << 4));
            }
            #pragma unroll
            for (int nt = 0; nt < 4; nt++) {
                uint32_t c = (uint32_t)(ks * 2) + bKadd;
                ldsm_x2(bf[nt], base + bOff[nt] + ((c ^ bR3[nt]) << 4));
            }
            #pragma unroll
            for (int mt = 0; mt < 4; mt++)
                #pragma unroll
                for (int nt = 0; nt < 4; nt++)
                    mma16816(acc[mt * 4 + nt], af[mt], bf[nt]);
        }
    };

    load_stage(0, 0); CP_COMMIT;
    load_stage(1, 1); CP_COMMIT;
    load_stage(2, 2); CP_COMMIT;
    for (int s = 0; s < S; s++) {
        CP_WAIT2;
        __syncthreads();
        if (s + 3 < S) load_stage(s + 3, (s + 3) & 3);
        CP_COMMIT;
        compute(s & 3);
    }

    int r0 = m0 + wm * 64 + (lane >> 2);
    int c0 = n0 + wn * 32 + 2 * (lane & 3);
    #pragma unroll
    for (int mt = 0; mt < 4; mt++) {
        #pragma unroll
        for (int nt = 0; nt < 4; nt++) {
            int row = r0 + mt * 16;
            int col = c0 + nt * 8;
            const float* a = acc[mt * 4 + nt];
            float b0 = bias[col], b1v = bias[col + 1];
            __half2 hh0, hh1;
            hh0.x = __float2half_rn(leaky(a[0] + b0));
            hh0.y = __float2half_rn(leaky(a[1] + b1v));
            hh1.x = __float2half_rn(leaky(a[2] + b0));
            hh1.y = __float2half_rn(leaky(a[3] + b1v));
            *(__half2*)(Ch + (size_t)row * ldc + col) = hh0;
            *(__half2*)(Ch + (size_t)(row + 8) * ldc + col) = hh1;
        }
    }
}

// ============================ GEMM3 (N=256) + fused einsum/scatter (R8-proven, exact) ============================
#define G3_STAGE 24576
#define G3_SPROD (4 * G3_STAGE)
#define G3_SEA   (G3_SPROD + 128 * 84 * 4)
#define G3_SRES  (G3_SEA + 128 * 8 * 4)
#define G3_SB3   (G3_SRES + 128 * 4 * 4)
#define G3_SMEM  (G3_SB3 + 256 * 4 + 256)

__global__ __launch_bounds__(512, 1)
void k_gemm3m(const __half* __restrict__ A, const __half* __restrict__ B)
{
    extern __shared__ char smem[];
    char* smc = (char*)(((uintptr_t)smem + 127) & ~(uintptr_t)127);
    uint32_t sbase = smem_to_u32(smc);
    float* sprod = (float*)(smc + G3_SPROD);
    float* sea   = (float*)(smc + G3_SEA);
    float* sres  = (float*)(smc + G3_SRES);
    float* sb3   = (float*)(smc + G3_SB3);
    int tid = threadIdx.x;
    int wid = tid >> 5, lane = tid & 31;
    int wm = wid >> 2, wn = wid & 3;
    int m0 = blockIdx.x * 128;
    const int S = HID / 32;

    float acc[16][4];
    #pragma unroll
    for (int i = 0; i < 16; i++)
        #pragma unroll
        for (int j = 0; j < 4; j++) acc[i][j] = 0.f;

    auto load_stage = [&](int s, int b) {
        uint32_t bo = sbase + (uint32_t)b * G3_STAGE;
        #pragma unroll
        for (int t = 0; t < 3; t++) {
            int i = tid + t * 512;
            if (i < 512) {
                int row = i >> 2, c = i & 3;
                cp16(bo + (uint32_t)row * 64 + (uint32_t)((c ^ (row & 3)) << 4),
                     A + (size_t)(m0 + row) * HID + s * 32 + c * 8);
            } else {
                int j = i - 512;
                int row = j >> 2, c = j & 3;
                cp16(bo + 8192u + (uint32_t)row * 64 + (uint32_t)((c ^ (row & 3)) << 4),
                     B + (size_t)row * HID + s * 32 + c * 8);
            }
        }
    };

    load_stage(0, 0); CP_COMMIT;
    load_stage(1, 1); CP_COMMIT;
    load_stage(2, 2); CP_COMMIT;

    for (int i = tid; i < 768; i += 512) {
        int r = i / 6, k = i - r * 6;
        sea[r * 8 + k] = g_sea[(size_t)(m0 + r) * 6 + k];
    }
    if (tid < 128) { sea[tid * 8 + 6] = 1.f; sea[tid * 8 + 7] = 1.f; }
    for (int i = tid; i < 256; i += 512) sb3[i] = g_b3p[i];
    if (tid < 512) sres[tid] = 0.f;
    __syncthreads();
    for (int i = tid; i < 128 * 83; i += 512) {
        int e = i / 83, p = i - e * 83;
        int pk = g_pidx[p];
        sprod[e * 84 + p] = sea[e * 8 + (pk & 255)] * sea[e * 8 + ((pk >> 8) & 255)]
                          * sea[e * 8 + ((pk >> 16) & 255)];
    }

    uint32_t aOff[2], aR3[2], bOff[8], bR3[8];
    {
        int arow_base = wm * 32 + ((lane >> 3) & 1) * 8 + (lane & 7);
        #pragma unroll
        for (int mt = 0; mt < 2; mt++) {
            int r = arow_base + mt * 16;
            aOff[mt] = (uint32_t)r * 64;
            aR3[mt] = (uint32_t)(r & 3);
        }
        int brow_base = wn * 64 + (lane & 7);
        #pragma unroll
        for (int nt = 0; nt < 8; nt++) {
            int r = brow_base + nt * 8;
            bOff[nt] = 8192u + (uint32_t)r * 64;
            bR3[nt] = (uint32_t)(r & 3);
        }
    }
    uint32_t aKadd = (uint32_t)(lane >> 4);
    uint32_t bKadd = (uint32_t)((lane >> 3) & 1);

    auto compute = [&](int b) {
        uint32_t base = sbase + (uint32_t)b * G3_STAGE;
        #pragma unroll
        for (int ks = 0; ks < 2; ks++) {
            uint32_t af[2][4], bf[8][2];
            #pragma unroll
            for (int mt = 0; mt < 2; mt++) {
                uint32_t c = (uint32_t)(ks * 2) + aKadd;
                ldsm_x4(af[mt], base + aOff[mt] + ((c ^ aR3[mt]) << 4));
            }
            #pragma unroll
            for (int nt = 0; nt < 8; nt++) {
                uint32_t c = (uint32_t)(ks * 2) + bKadd;
                ldsm_x2(bf[nt], base + bOff[nt] + ((c ^ bR3[nt]) << 4));
            }
            #pragma unroll
            for (int mt = 0; mt < 2; mt++)
                #pragma unroll
                for (int nt = 0; nt < 8; nt++)
                    mma16816(acc[mt * 8 + nt], af[mt], bf[nt]);
        }
    };

    for (int s = 0; s < S; s++) {
        CP_WAIT2;
        __syncthreads();
        if (s + 3 < S) load_stage(s + 3, (s + 3) & 3);
        CP_COMMIT;
        compute(s & 3);
    }
    __syncthreads();

    int lr = lane >> 2;
    int lc2 = 2 * (lane & 3);
    #pragma unroll
    for (int mt = 0; mt < 2; mt++) {
        int row0 = wm * 32 + mt * 16 + lr;
        int row1 = row0 + 8;
        float p0[3] = {0.f, 0.f, 0.f}, p1[3] = {0.f, 0.f, 0.f};
        #pragma unroll
        for (int nt = 0; nt < 8; nt++) {
            const float* a = acc[mt * 8 + nt];
            int colb = wn * 64 + nt * 8 + lc2;
            #pragma unroll
            for (int q = 0; q < 2; q++) {
                int j = colb + q;
                if (j < MSG) {
                    int k = j / 83;
                    int p = j - k * 83;
                    float w0 = a[q]     + sb3[j];
                    float w1 = a[2 + q] + sb3[j];
                    p0[k] += w0 * sprod[row0 * 84 + p];
                    p1[k] += w1 * sprod[row1 * 84 + p];
                }
            }
        }
        #pragma unroll
        for (int k = 0; k < 3; k++) {
            atomicAdd(&sres[row0 * 4 + k], p0[k]);
            atomicAdd(&sres[row1 * 4 + k], p1[k]);
        }
    }
    __syncthreads();

    if (tid < 128) {
        int e = m0 + tid;
        int s = g_ssrc[e], d = g_sdst[e];
        float r0 = sres[tid * 4 + 0], r1 = sres[tid * 4 + 1], r2 = sres[tid * 4 + 2];
        atomicAdd(&g_agg[d * 3 + 0],  r0);
        atomicAdd(&g_agg[d * 3 + 1],  r1);
        atomicAdd(&g_agg[d * 3 + 2],  r2);
        atomicAdd(&g_agg[s * 3 + 0], -r0);
        atomicAdd(&g_agg[s * 3 + 1], -r1);
        atomicAdd(&g_agg[s * 3 + 2], -r2);
    }
}

// ============================ node update: LN(19)+MLP ============================
__global__ void k_update(const float* __restrict__ x,
                         const float* __restrict__ ln_g, const float* __restrict__ ln_b,
                         const float* __restrict__ uW1, const float* __restrict__ ub1,
                         const float* __restrict__ uW2, const float* __restrict__ ub2,
                         const float* __restrict__ uW3, const float* __restrict__ ub3,
                         float* __restrict__ out) {
    __shared__ float sW1[19 * 18], sW2[18 * 17], sW3[17 * 16];
    __shared__ float sb1[18], sb2[17], sb3[16], sg[19], sbt[19];
    int t = threadIdx.x;
    for (int i = t; i < 19 * 18; i += blockDim.x) sW1[i] = uW1[i];
    for (int i = t; i < 18 * 17; i += blockDim.x) sW2[i] = uW2[i];
    for (int i = t; i < 17 * 16; i += blockDim.x) sW3[i] = uW3[i];
    if (t < 18) sb1[t] = ub1[t];
    if (t < 17) sb2[t] = ub2[t];
    if (t < 16) sb3[t] = ub3[t];
    if (t < 19) { sg[t] = ln_g[t]; sbt[t] = ln_b[t]; }
    __syncthreads();

    int node = blockIdx.x * blockDim.x + t;
    if (node >= NNODES) return;

    float h[19];
    #pragma unroll
    for (int i = 0; i < 16; i++) h[i] = x[node * 16 + i];
    #pragma unroll
    for (int k = 0; k < 3; k++) h[16 + k] = g_agg[node * 3 + k];

    float mu = 0.f;
    #pragma unroll
    for (int i = 0; i < 19; i++) mu += h[i];
    mu *= (1.f / 19.f);
    float var = 0.f;
    #pragma unroll
    for (int i = 0; i < 19; i++) { float dlt = h[i] - mu; var += dlt * dlt; }
    var *= (1.f / 19.f);
    float rs = rsqrtf(var + LN_EPS);
    float hn[19];
    #pragma unroll
    for (int i = 0; i < 19; i++) hn[i] = (h[i] - mu) * rs * sg[i] + sbt[i];

    float t1[18];
    #pragma unroll
    for (int j = 0; j < 18; j++) {
        float acc = sb1[j];
        #pragma unroll
        for (int i = 0; i < 19; i++) acc += hn[i] * sW1[i * 18 + j];
        t1[j] = leaky(acc);
    }
    float t2[17];
    #pragma unroll
    for (int j = 0; j < 17; j++) {
        float acc = sb2[j];
        #pragma unroll
        for (int i = 0; i < 18; i++) acc += t1[i] * sW2[i * 17 + j];
        t2[j] = leaky(acc);
    }
    #pragma unroll
    for (int j = 0; j < 16; j++) {
        float acc = sb3[j];
        #pragma unroll
        for (int i = 0; i < 17; i++) acc += t2[i] * sW3[i * 16 + j];
        out[node * 16 + j] = acc;
    }
}

// ============================ launch ============================
extern "C" void kernel_launch(void* const* d_in, const int* in_sizes, int n_in,
                              void* d_out, int out_size) {
    const float* x    = (const float*)d_in[0];
    const float* ea   = (const float*)d_in[1];
    const float* mW1  = (const float*)d_in[2];
    const float* mb1  = (const float*)d_in[3];
    const float* mW2  = (const float*)d_in[4];
    const float* mb2  = (const float*)d_in[5];
    const float* mW3  = (const float*)d_in[6];
    const float* mb3  = (const float*)d_in[7];
    const float* ln_g = (const float*)d_in[8];
    const float* ln_b = (const float*)d_in[9];
    const float* uW1  = (const float*)d_in[10];
    const float* ub1  = (const float*)d_in[11];
    const float* uW2  = (const float*)d_in[12];
    const float* ub2  = (const float*)d_in[13];
    const float* uW3  = (const float*)d_in[14];
    const float* ub3  = (const float*)d_in[15];
    const int*   eidx = (const int*)d_in[16];

    int E = in_sizes[1] / 6;               // 131072
    const int* src = eidx;
    const int* dst = eidx + E;
    int esel = E / 2;                      // 65536
    int NB = (E + 1023) / 1024;

    __half *p_h1, *p_h2, *p_w2t, *p_w3t;
    cudaGetSymbolAddress((void**)&p_h1,  g_h1);
    cudaGetSymbolAddress((void**)&p_h2,  g_h2);
    cudaGetSymbolAddress((void**)&p_w2t, g_w2t);
    cudaGetSymbolAddress((void**)&p_w3t, g_w3t);

    cudaFuncSetAttribute(k_gemm_mma, cudaFuncAttributeMaxDynamicSharedMemorySize, GEMM_SMEM);
    cudaFuncSetAttribute(k_gemm3m,  cudaFuncAttributeMaxDynamicSharedMemorySize, G3_SMEM);

    k_misc   <<<(NNODES * 3 + 255) / 256, 256>>>(mb3);
    {
        dim3 bt(256); dim3 gt2(HID / 32, HID / 32);
        k_tw2<<<gt2, bt>>>(mW2);
        dim3 gt3(MSGP / 32, HID / 32);
        k_tw3<<<gt3, bt>>>(mW3);
    }
    k_count  <<<NB, 1024>>>(src, dst, E);
    k_scan   <<<1, 1024>>>(NB);
    k_scatter<<<NB, 1024>>>(src, dst, ea, E);

    k_layer1v<<<esel / 8, 256>>>(mW1, mb1);

    // GEMM2: h2 = leaky(h1 @ W2 + b2), fp16 out (R8-proven shape)
    dim3 g2(HID / 128, esel / 128);
    k_gemm_mma<<<g2, 256, GEMM_SMEM>>>(p_h1, p_w2t, mb2, p_h2, HID, HID);

    // GEMM3 + einsum + antisymmetric scatter
    k_gemm3m<<<esel / 128, 512, G3_SMEM>>>(p_h2, p_w3t);

    k_update<<<(NNODES + 127) / 128, 128>>>(x, ln_g, ln_b, uW1, ub1, uW2, ub2,
                                            uW3, ub3, (float*)d_out);
}

// round 13
// speedup vs baseline: 1.0808x; 1.0808x over previous
#include <cuda_runtime.h>
#include <cuda_fp16.h>
#include <cstdint>

#define NNODES   8192
#define EMAX     131072
#define ESEL     65536
#define HID      768
#define MSG      249
#define MSGP     256
#define LN_EPS   1e-5f

// ============================ PTX helpers (baseline, sm_80+) ============================
__device__ __forceinline__ uint32_t smem_to_u32(const void* p) {
    uint32_t a;
    asm("{ .reg .u64 t; cvta.to.shared.u64 t, %1; cvt.u32.u64 %0, t; }" : "=r"(a) : "l"(p));
    return a;
}
__device__ __forceinline__ void cp16(uint32_t s, const void* g) {
    asm volatile("cp.async.cg.shared.global [%0], [%1], 16;" :: "r"(s), "l"(g));
}
#define CP_COMMIT  asm volatile("cp.async.commit_group;" ::: "memory")
#define CP_WAIT2   asm volatile("cp.async.wait_group 2;" ::: "memory")

__device__ __forceinline__ void ldsm_x4(uint32_t* r, uint32_t addr) {
    asm volatile("ldmatrix.sync.aligned.m8n8.x4.shared.b16 {%0,%1,%2,%3}, [%4];"
        : "=r"(r[0]), "=r"(r[1]), "=r"(r[2]), "=r"(r[3]) : "r"(addr));
}
__device__ __forceinline__ void ldsm_x2(uint32_t* r, uint32_t addr) {
    asm volatile("ldmatrix.sync.aligned.m8n8.x2.shared.b16 {%0,%1}, [%2];"
        : "=r"(r[0]), "=r"(r[1]) : "r"(addr));
}
__device__ __forceinline__ void mma16816(float* d, const uint32_t* a, const uint32_t* b) {
    asm volatile("mma.sync.aligned.m16n8k16.row.col.f32.f16.f16.f32 "
        "{%0,%1,%2,%3}, {%4,%5,%6,%7}, {%8,%9}, {%0,%1,%2,%3};"
        : "+f"(d[0]), "+f"(d[1]), "+f"(d[2]), "+f"(d[3])
        : "r"(a[0]), "r"(a[1]), "r"(a[2]), "r"(a[3]), "r"(b[0]), "r"(b[1]));
}

// ============================ scratch ============================
__device__ __half g_h1[(size_t)ESEL * HID];
__device__ __half g_h2[(size_t)ESEL * HID];
__device__ __half g_w2t[HID * HID];
__device__ __half g_w3t[MSGP * HID];
__device__ float g_b3p[MSGP];
__device__ float g_sea[ESEL * 6];
__device__ int   g_ssrc[ESEL];
__device__ int   g_sdst[ESEL];
__device__ float g_agg[NNODES * 3];
__device__ int   g_bcnt[1024];
__device__ int   g_boff[1024];
__device__ int   g_pidx[83];

__device__ __forceinline__ float leaky(float v) { return v > 0.f ? v : 0.01f * v; }

// ============================ edge compaction (src < dst) ============================
__global__ void k_count(const int* __restrict__ src, const int* __restrict__ dst, int E) {
    int e = blockIdx.x * blockDim.x + threadIdx.x;
    int pred = (e < E) && (src[e] < dst[e]);
    unsigned bal = __ballot_sync(0xffffffffu, pred);
    __shared__ int wc[32];
    int wid = threadIdx.x >> 5, lane = threadIdx.x & 31;
    if (lane == 0) wc[wid] = __popc(bal);
    __syncthreads();
    if (threadIdx.x == 0) {
        int nmw = blockDim.x >> 5, s = 0;
        for (int i = 0; i < nmw; i++) s += wc[i];
        g_bcnt[blockIdx.x] = s;
    }
}
__global__ void k_scan(int nb) {
    __shared__ int s[1024];
    int t = threadIdx.x;
    if (t < nb) s[t] = g_bcnt[t];
    __syncthreads();
    if (t == 0) { int acc = 0; for (int i = 0; i < nb; i++) { int v = s[i]; s[i] = acc; acc += v; } }
    __syncthreads();
    if (t < nb) g_boff[t] = s[t];
}
__global__ void k_scatter(const int* __restrict__ src, const int* __restrict__ dst,
                          const float* __restrict__ ea, int E) {
    int e = blockIdx.x * blockDim.x + threadIdx.x;
    int pred = (e < E) && (src[e] < dst[e]);
    unsigned bal = __ballot_sync(0xffffffffu, pred);
    __shared__ int wc[32], ws[32];
    int wid = threadIdx.x >> 5, lane = threadIdx.x & 31;
    if (lane == 0) wc[wid] = __popc(bal);
    __syncthreads();
    if (threadIdx.x == 0) {
        int nmw = blockDim.x >> 5, acc = 0;
        for (int i = 0; i < nmw; i++) { ws[i] = acc; acc += wc[i]; }
    }
    __syncthreads();
    if (pred) {
        int idx = g_boff[blockIdx.x] + ws[wid] + __popc(bal & ((1u << lane) - 1u));
        g_ssrc[idx] = src[e];
        g_sdst[idx] = dst[e];
        #pragma unroll
        for (int k = 0; k < 6; k++) g_sea[idx * 6 + k] = ea[(size_t)e * 6 + k];
    }
}

// ============================ prep: coalesced transposes + misc ============================
__global__ __launch_bounds__(256)
void k_tw2(const float* __restrict__ W2) {
    __shared__ float tile[32][33];
    int bx = blockIdx.x * 32, by = blockIdx.y * 32;
    int tx = threadIdx.x & 31, ty = threadIdx.x >> 5;
    #pragma unroll
    for (int i = 0; i < 4; i++) {
        int k = by + ty + i * 8;
        tile[ty + i * 8][tx] = W2[(size_t)k * HID + bx + tx];
    }
    __syncthreads();
    #pragma unroll
    for (int i = 0; i < 4; i++) {
        int n = bx + ty + i * 8;
        g_w2t[(size_t)n * HID + by + tx] = __float2half_rn(tile[tx][ty + i * 8]);
    }
}
__global__ __launch_bounds__(256)
void k_tw3(const float* __restrict__ W3) {
    __shared__ float tile[32][33];
    int bx = blockIdx.x * 32, by = blockIdx.y * 32;
    int tx = threadIdx.x & 31, ty = threadIdx.x >> 5;
    #pragma unroll
    for (int i = 0; i < 4; i++) {
        int k = by + ty + i * 8;
        int n = bx + tx;
        tile[ty + i * 8][tx] = (n < MSG) ? W3[(size_t)k * MSG + n] : 0.f;
    }
    __syncthreads();
    #pragma unroll
    for (int i = 0; i < 4; i++) {
        int n = bx + ty + i * 8;
        g_w3t[(size_t)n * HID + by + tx] = __float2half_rn(tile[tx][ty + i * 8]);
    }
}
__global__ void k_misc(const float* __restrict__ b3) {
    int idx = blockIdx.x * blockDim.x + threadIdx.x;
    if (idx < MSGP) g_b3p[idx] = (idx < MSG) ? b3[idx] : 0.f;
    if (idx < NNODES * 3) g_agg[idx] = 0.f;
    if (idx == 0) {
        int p = 0;
        for (int a = 0; a < 6; a++) g_pidx[p++] = a | (6 << 8) | (6 << 16);
        for (int a = 0; a < 6; a++)
            for (int b = a; b < 6; b++) g_pidx[p++] = a | (b << 8) | (6 << 16);
        for (int a = 0; a < 6; a++)
            for (int b = a; b < 6; b++)
                for (int c = b; c < 6; c++) g_pidx[p++] = a | (b << 8) | (c << 16);
    }
}

// ============================ layer1 (R8-proven): [Esel,6]@[6,768], leaky, fp16 out ============================
#define L1_EPB 8
__global__ void k_layer1(const float* __restrict__ W1, const float* __restrict__ b1, int esel) {
    int e0 = blockIdx.x * L1_EPB;
    __shared__ float ea[L1_EPB][6];
    int t = threadIdx.x;
    if (t < L1_EPB * 6) ea[t / 6][t % 6] = g_sea[e0 * 6 + t];
    __syncthreads();
    for (int n = t; n < HID; n += blockDim.x) {
        float w[6];
        #pragma unroll
        for (int k = 0; k < 6; k++) w[k] = W1[k * HID + n];
        float bb = b1[n];
        #pragma unroll
        for (int e = 0; e < L1_EPB; e++) {
            float acc = bb;
            #pragma unroll
            for (int k = 0; k < 6; k++) acc += ea[e][k] * w[k];
            g_h1[(size_t)(e0 + e) * HID + n] = __float2half_rn(leaky(acc));
        }
    }
}

// ============================ GEMM2: warp-MMA single-fp16 (R8-proven, exact) ============================
#define GSTAGE    16384
#define GEMM_SMEM (4 * GSTAGE + 128)

__global__ __launch_bounds__(256, 1)
void k_gemm_mma(const __half* __restrict__ A, const __half* __restrict__ B,
                const float* __restrict__ bias, __half* __restrict__ Ch,
                int K, int ldc)
{
    extern __shared__ char smem[];
    uint32_t sbase = (smem_to_u32(smem) + 127) & ~127u;
    int tid = threadIdx.x;
    int wid = tid >> 5, lane = tid & 31;
    int wm = wid >> 2, wn = wid & 3;
    int m0 = blockIdx.y * 128, n0 = blockIdx.x * 128;
    int S = K / 32;

    float acc[16][4];
    #pragma unroll
    for (int i = 0; i < 16; i++)
        #pragma unroll
        for (int j = 0; j < 4; j++) acc[i][j] = 0.f;

    auto load_stage = [&](int s, int b) {
        uint32_t bo = sbase + (uint32_t)b * GSTAGE;
        #pragma unroll
        for (int t = 0; t < 4; t++) {
            int i   = tid + t * 256;
            int mat = i >> 9;
            int rem = i & 511;
            int row = rem >> 2;
            int c   = rem & 3;
            const __half* g = (mat == 0 ? A + (size_t)(m0 + row) * K
                                        : B + (size_t)(n0 + row) * K);
            g += s * 32 + c * 8;
            uint32_t dstr = bo + (uint32_t)mat * 8192 + (uint32_t)row * 64
                          + (uint32_t)((c ^ (row & 3)) << 4);
            cp16(dstr, g);
        }
    };

    uint32_t aOff[4], aR3[4], bOff[4], bR3[4];
    {
        int arow_base = wm * 64 + ((lane >> 3) & 1) * 8 + (lane & 7);
        #pragma unroll
        for (int mt = 0; mt < 4; mt++) {
            int r = arow_base + mt * 16;
            aOff[mt] = (uint32_t)r * 64;
            aR3[mt] = (uint32_t)(r & 3);
        }
        int brow_base = wn * 32 + (lane & 7);
        #pragma unroll
        for (int nt = 0; nt < 4; nt++) {
            int r = brow_base + nt * 8;
            bOff[nt] = 8192u + (uint32_t)r * 64;
            bR3[nt] = (uint32_t)(r & 3);
        }
    }
    uint32_t aKadd = (uint32_t)(lane >> 4);
    uint32_t bKadd = (uint32_t)((lane >> 3) & 1);

    auto compute = [&](int b) {
        uint32_t base = sbase + (uint32_t)b * GSTAGE;
        #pragma unroll
        for (int ks = 0; ks < 2; ks++) {
            uint32_t af[4][4], bf[4][2];
            #pragma unroll
            for (int mt = 0; mt < 4; mt++) {
                uint32_t c = (uint32_t)(ks * 2) + aKadd;
                ldsm_x4(af[mt], base + aOff[mt] + ((c ^ aR3[mt]) << 4));
            }
            #pragma unroll
            for (int nt = 0; nt < 4; nt++) {
                uint32_t c = (uint32_t)(ks * 2) + bKadd;
                ldsm_x2(bf[nt], base + bOff[nt] + ((c ^ bR3[nt]) << 4));
            }
            #pragma unroll
            for (int mt = 0; mt < 4; mt++)
                #pragma unroll
                for (int nt = 0; nt < 4; nt++)
                    mma16816(acc[mt * 4 + nt], af[mt], bf[nt]);
        }
    };

    load_stage(0, 0); CP_COMMIT;
    load_stage(1, 1); CP_COMMIT;
    load_stage(2, 2); CP_COMMIT;
    for (int s = 0; s < S; s++) {
        CP_WAIT2;
        __syncthreads();
        if (s + 3 < S) load_stage(s + 3, (s + 3) & 3);
        CP_COMMIT;
        compute(s & 3);
    }

    int r0 = m0 + wm * 64 + (lane >> 2);
    int c0 = n0 + wn * 32 + 2 * (lane & 3);
    #pragma unroll
    for (int mt = 0; mt < 4; mt++) {
        #pragma unroll
        for (int nt = 0; nt < 4; nt++) {
            int row = r0 + mt * 16;
            int col = c0 + nt * 8;
            const float* a = acc[mt * 4 + nt];
            float b0 = bias[col], b1v = bias[col + 1];
            __half2 hh0, hh1;
            hh0.x = __float2half_rn(leaky(a[0] + b0));
            hh0.y = __float2half_rn(leaky(a[1] + b1v));
            hh1.x = __float2half_rn(leaky(a[2] + b0));
            hh1.y = __float2half_rn(leaky(a[3] + b1v));
            *(__half2*)(Ch + (size_t)row * ldc + col) = hh0;
            *(__half2*)(Ch + (size_t)(row + 8) * ldc + col) = hh1;
        }
    }
}

// ============================ GEMM3 (N=256) + fused einsum/scatter (R8-proven, exact) ============================
#define G3_STAGE 24576
#define G3_SPROD (4 * G3_STAGE)
#define G3_SEA   (G3_SPROD + 128 * 84 * 4)
#define G3_SRES  (G3_SEA + 128 * 8 * 4)
#define G3_SB3   (G3_SRES + 128 * 4 * 4)
#define G3_SMEM  (G3_SB3 + 256 * 4 + 256)

__global__ __launch_bounds__(512, 1)
void k_gemm3m(const __half* __restrict__ A, const __half* __restrict__ B)
{
    extern __shared__ char smem[];
    char* smc = (char*)(((uintptr_t)smem + 127) & ~(uintptr_t)127);
    uint32_t sbase = smem_to_u32(smc);
    float* sprod = (float*)(smc + G3_SPROD);
    float* sea   = (float*)(smc + G3_SEA);
    float* sres  = (float*)(smc + G3_SRES);
    float* sb3   = (float*)(smc + G3_SB3);
    int tid = threadIdx.x;
    int wid = tid >> 5, lane = tid & 31;
    int wm = wid >> 2, wn = wid & 3;
    int m0 = blockIdx.x * 128;
    const int S = HID / 32;

    float acc[16][4];
    #pragma unroll
    for (int i = 0; i < 16; i++)
        #pragma unroll
        for (int j = 0; j < 4; j++) acc[i][j] = 0.f;

    auto load_stage = [&](int s, int b) {
        uint32_t bo = sbase + (uint32_t)b * G3_STAGE;
        #pragma unroll
        for (int t = 0; t < 3; t++) {
            int i = tid + t * 512;
            if (i < 512) {
                int row = i >> 2, c = i & 3;
                cp16(bo + (uint32_t)row * 64 + (uint32_t)((c ^ (row & 3)) << 4),
                     A + (size_t)(m0 + row) * HID + s * 32 + c * 8);
            } else {
                int j = i - 512;
                int row = j >> 2, c = j & 3;
                cp16(bo + 8192u + (uint32_t)row * 64 + (uint32_t)((c ^ (row & 3)) << 4),
                     B + (size_t)row * HID + s * 32 + c * 8);
            }
        }
    };

    load_stage(0, 0); CP_COMMIT;
    load_stage(1, 1); CP_COMMIT;
    load_stage(2, 2); CP_COMMIT;

    for (int i = tid; i < 768; i += 512) {
        int r = i / 6, k = i - r * 6;
        sea[r * 8 + k] = g_sea[(size_t)(m0 + r) * 6 + k];
    }
    if (tid < 128) { sea[tid * 8 + 6] = 1.f; sea[tid * 8 + 7] = 1.f; }
    for (int i = tid; i < 256; i += 512) sb3[i] = g_b3p[i];
    if (tid < 512) sres[tid] = 0.f;
    __syncthreads();
    for (int i = tid; i < 128 * 83; i += 512) {
        int e = i / 83, p = i - e * 83;
        int pk = g_pidx[p];
        sprod[e * 84 + p] = sea[e * 8 + (pk & 255)] * sea[e * 8 + ((pk >> 8) & 255)]
                          * sea[e * 8 + ((pk >> 16) & 255)];
    }

    uint32_t aOff[2], aR3[2], bOff[8], bR3[8];
    {
        int arow_base = wm * 32 + ((lane >> 3) & 1) * 8 + (lane & 7);
        #pragma unroll
        for (int mt = 0; mt < 2; mt++) {
            int r = arow_base + mt * 16;
            aOff[mt] = (uint32_t)r * 64;
            aR3[mt] = (uint32_t)(r & 3);
        }
        int brow_base = wn * 64 + (lane & 7);
        #pragma unroll
        for (int nt = 0; nt < 8; nt++) {
            int r = brow_base + nt * 8;
            bOff[nt] = 8192u + (uint32_t)r * 64;
            bR3[nt] = (uint32_t)(r & 3);
        }
    }
    uint32_t aKadd = (uint32_t)(lane >> 4);
    uint32_t bKadd = (uint32_t)((lane >> 3) & 1);

    auto compute = [&](int b) {
        uint32_t base = sbase + (uint32_t)b * G3_STAGE;
        #pragma unroll
        for (int ks = 0; ks < 2; ks++) {
            uint32_t af[2][4], bf[8][2];
            #pragma unroll
            for (int mt = 0; mt < 2; mt++) {
                uint32_t c = (uint32_t)(ks * 2) + aKadd;
                ldsm_x4(af[mt], base + aOff[mt] + ((c ^ aR3[mt]) << 4));
            }
            #pragma unroll
            for (int nt = 0; nt < 8; nt++) {
                uint32_t c = (uint32_t)(ks * 2) + bKadd;
                ldsm_x2(bf[nt], base + bOff[nt] + ((c ^ bR3[nt]) << 4));
            }
            #pragma unroll
            for (int mt = 0; mt < 2; mt++)
                #pragma unroll
                for (int nt = 0; nt < 8; nt++)
                    mma16816(acc[mt * 8 + nt], af[mt], bf[nt]);
        }
    };

    for (int s = 0; s < S; s++) {
        CP_WAIT2;
        __syncthreads();
        if (s + 3 < S) load_stage(s + 3, (s + 3) & 3);
        CP_COMMIT;
        compute(s & 3);
    }
    __syncthreads();

    int lr = lane >> 2;
    int lc2 = 2 * (lane & 3);
    #pragma unroll
    for (int mt = 0; mt < 2; mt++) {
        int row0 = wm * 32 + mt * 16 + lr;
        int row1 = row0 + 8;
        float p0[3] = {0.f, 0.f, 0.f}, p1[3] = {0.f, 0.f, 0.f};
        #pragma unroll
        for (int nt = 0; nt < 8; nt++) {
            const float* a = acc[mt * 8 + nt];
            int colb = wn * 64 + nt * 8 + lc2;
            #pragma unroll
            for (int q = 0; q < 2; q++) {
                int j = colb + q;
                if (j < MSG) {
                    int k = j / 83;
                    int p = j - k * 83;
                    float w0 = a[q]     + sb3[j];
                    float w1 = a[2 + q] + sb3[j];
                    p0[k] += w0 * sprod[row0 * 84 + p];
                    p1[k] += w1 * sprod[row1 * 84 + p];
                }
            }
        }
        #pragma unroll
        for (int k = 0; k < 3; k++) {
            atomicAdd(&sres[row0 * 4 + k], p0[k]);
            atomicAdd(&sres[row1 * 4 + k], p1[k]);
        }
    }
    __syncthreads();

    if (tid < 128) {
        int e = m0 + tid;
        int s = g_ssrc[e], d = g_sdst[e];
        float r0 = sres[tid * 4 + 0], r1 = sres[tid * 4 + 1], r2 = sres[tid * 4 + 2];
        atomicAdd(&g_agg[d * 3 + 0],  r0);
        atomicAdd(&g_agg[d * 3 + 1],  r1);
        atomicAdd(&g_agg[d * 3 + 2],  r2);
        atomicAdd(&g_agg[s * 3 + 0], -r0);
        atomicAdd(&g_agg[s * 3 + 1], -r1);
        atomicAdd(&g_agg[s * 3 + 2], -r2);
    }
}

// ============================ node update: LN(19)+MLP ============================
__global__ void k_update(const float* __restrict__ x,
                         const float* __restrict__ ln_g, const float* __restrict__ ln_b,
                         const float* __restrict__ uW1, const float* __restrict__ ub1,
                         const float* __restrict__ uW2, const float* __restrict__ ub2,
                         const float* __restrict__ uW3, const float* __restrict__ ub3,
                         float* __restrict__ out) {
    __shared__ float sW1[19 * 18], sW2[18 * 17], sW3[17 * 16];
    __shared__ float sb1[18], sb2[17], sb3[16], sg[19], sbt[19];
    int t = threadIdx.x;
    for (int i = t; i < 19 * 18; i += blockDim.x) sW1[i] = uW1[i];
    for (int i = t; i < 18 * 17; i += blockDim.x) sW2[i] = uW2[i];
    for (int i = t; i < 17 * 16; i += blockDim.x) sW3[i] = uW3[i];
    if (t < 18) sb1[t] = ub1[t];
    if (t < 17) sb2[t] = ub2[t];
    if (t < 16) sb3[t] = ub3[t];
    if (t < 19) { sg[t] = ln_g[t]; sbt[t] = ln_b[t]; }
    __syncthreads();

    int node = blockIdx.x * blockDim.x + t;
    if (node >= NNODES) return;

    float h[19];
    #pragma unroll
    for (int i = 0; i < 16; i++) h[i] = x[node * 16 + i];
    #pragma unroll
    for (int k = 0; k < 3; k++) h[16 + k] = g_agg[node * 3 + k];

    float mu = 0.f;
    #pragma unroll
    for (int i = 0; i < 19; i++) mu += h[i];
    mu *= (1.f / 19.f);
    float var = 0.f;
    #pragma unroll
    for (int i = 0; i < 19; i++) { float dlt = h[i] - mu; var += dlt * dlt; }
    var *= (1.f / 19.f);
    float rs = rsqrtf(var + LN_EPS);
    float hn[19];
    #pragma unroll
    for (int i = 0; i < 19; i++) hn[i] = (h[i] - mu) * rs * sg[i] + sbt[i];

    float t1[18];
    #pragma unroll
    for (int j = 0; j < 18; j++) {
        float acc = sb1[j];
        #pragma unroll
        for (int i = 0; i < 19; i++) acc += hn[i] * sW1[i * 18 + j];
        t1[j] = leaky(acc);
    }
    float t2[17];
    #pragma unroll
    for (int j = 0; j < 17; j++) {
        float acc = sb2[j];
        #pragma unroll
        for (int i = 0; i < 18; i++) acc += t1[i] * sW2[i * 17 + j];
        t2[j] = leaky(acc);
    }
    #pragma unroll
    for (int j = 0; j < 16; j++) {
        float acc = sb3[j];
        #pragma unroll
        for (int i = 0; i < 17; i++) acc += t2[i] * sW3[i * 16 + j];
        out[node * 16 + j] = acc;
    }
}

// ============================ launch ============================
extern "C" void kernel_launch(void* const* d_in, const int* in_sizes, int n_in,
                              void* d_out, int out_size) {
    const float* x    = (const float*)d_in[0];
    const float* ea   = (const float*)d_in[1];
    const float* mW1  = (const float*)d_in[2];
    const float* mb1  = (const float*)d_in[3];
    const float* mW2  = (const float*)d_in[4];
    const float* mb2  = (const float*)d_in[5];
    const float* mW3  = (const float*)d_in[6];
    const float* mb3  = (const float*)d_in[7];
    const float* ln_g = (const float*)d_in[8];
    const float* ln_b = (const float*)d_in[9];
    const float* uW1  = (const float*)d_in[10];
    const float* ub1  = (const float*)d_in[11];
    const float* uW2  = (const float*)d_in[12];
    const float* ub2  = (const float*)d_in[13];
    const float* uW3  = (const float*)d_in[14];
    const float* ub3  = (const float*)d_in[15];
    const int*   eidx = (const int*)d_in[16];

    int E = in_sizes[1] / 6;               // 131072
    const int* src = eidx;
    const int* dst = eidx + E;
    int esel = E / 2;                      // 65536
    int NB = (E + 1023) / 1024;

    __half *p_h1, *p_h2, *p_w2t, *p_w3t;
    cudaGetSymbolAddress((void**)&p_h1,  g_h1);
    cudaGetSymbolAddress((void**)&p_h2,  g_h2);
    cudaGetSymbolAddress((void**)&p_w2t, g_w2t);
    cudaGetSymbolAddress((void**)&p_w3t, g_w3t);

    cudaFuncSetAttribute(k_gemm_mma, cudaFuncAttributeMaxDynamicSharedMemorySize, GEMM_SMEM);
    cudaFuncSetAttribute(k_gemm3m,  cudaFuncAttributeMaxDynamicSharedMemorySize, G3_SMEM);

    k_misc   <<<(NNODES * 3 + 255) / 256, 256>>>(mb3);
    {
        dim3 bt(256); dim3 gt2(HID / 32, HID / 32);
        k_tw2<<<gt2, bt>>>(mW2);
        dim3 gt3(MSGP / 32, HID / 32);
        k_tw3<<<gt3, bt>>>(mW3);
    }
    k_count  <<<NB, 1024>>>(src, dst, E);
    k_scan   <<<1, 1024>>>(NB);
    k_scatter<<<NB, 1024>>>(src, dst, ea, E);

    k_layer1 <<<esel / L1_EPB, 256>>>(mW1, mb1, esel);

    // GEMM2: h2 = leaky(h1 @ W2 + b2), fp16 out (R8-proven shape)
    dim3 g2(HID / 128, esel / 128);
    k_gemm_mma<<<g2, 256, GEMM_SMEM>>>(p_h1, p_w2t, mb2, p_h2, HID, HID);

    // GEMM3 + einsum + antisymmetric scatter
    k_gemm3m<<<esel / 128, 512, G3_SMEM>>>(p_h2, p_w3t);

    k_update<<<(NNODES + 127) / 128, 128>>>(x, ln_g, ln_b, uW1, ub1, uW2, ub2,
                                            uW3, ub3, (float*)d_out);
}

// round 14
// speedup vs baseline: 1.2220x; 1.1307x over previous
#include <cuda_runtime.h>
#include <cuda_fp16.h>
#include <cstdint>

#define NNODES   8192
#define EMAX     131072
#define ESEL     65536
#define HID      768
#define MSG      249
#define MSGP     256
#define LN_EPS   1e-5f

// ============================ PTX helpers (baseline, sm_80+) ============================
__device__ __forceinline__ uint32_t smem_to_u32(const void* p) {
    uint32_t a;
    asm("{ .reg .u64 t; cvta.to.shared.u64 t, %1; cvt.u32.u64 %0, t; }" : "=r"(a) : "l"(p));
    return a;
}
__device__ __forceinline__ void cp16(uint32_t s, const void* g) {
    asm volatile("cp.async.cg.shared.global [%0], [%1], 16;" :: "r"(s), "l"(g));
}
#define CP_COMMIT  asm volatile("cp.async.commit_group;" ::: "memory")
#define CP_WAIT2   asm volatile("cp.async.wait_group 2;" ::: "memory")

__device__ __forceinline__ void ldsm_x4(uint32_t* r, uint32_t addr) {
    asm volatile("ldmatrix.sync.aligned.m8n8.x4.shared.b16 {%0,%1,%2,%3}, [%4];"
        : "=r"(r[0]), "=r"(r[1]), "=r"(r[2]), "=r"(r[3]) : "r"(addr));
}
__device__ __forceinline__ void ldsm_x2(uint32_t* r, uint32_t addr) {
    asm volatile("ldmatrix.sync.aligned.m8n8.x2.shared.b16 {%0,%1}, [%2];"
        : "=r"(r[0]), "=r"(r[1]) : "r"(addr));
}
__device__ __forceinline__ void mma16816(float* d, const uint32_t* a, const uint32_t* b) {
    asm volatile("mma.sync.aligned.m16n8k16.row.col.f32.f16.f16.f32 "
        "{%0,%1,%2,%3}, {%4,%5,%6,%7}, {%8,%9}, {%0,%1,%2,%3};"
        : "+f"(d[0]), "+f"(d[1]), "+f"(d[2]), "+f"(d[3])
        : "r"(a[0]), "r"(a[1]), "r"(a[2]), "r"(a[3]), "r"(b[0]), "r"(b[1]));
}

// ============================ scratch ============================
__device__ __half g_h1[(size_t)ESEL * HID];
__device__ __half g_h2[(size_t)ESEL * HID];
__device__ __half g_w2t[HID * HID];
__device__ __half g_w3t[MSGP * HID];
__device__ float g_b3p[MSGP];
__device__ float g_sea[ESEL * 6];
__device__ int   g_ssrc[ESEL];
__device__ int   g_sdst[ESEL];
__device__ float g_agg[NNODES * 3];
__device__ int   g_bcnt[1024];
__device__ int   g_boff[1024];
__device__ int   g_pidx[83];

__device__ __forceinline__ float leaky(float v) { return v > 0.f ? v : 0.01f * v; }

// ============================ edge compaction (src < dst) ============================
__global__ void k_count(const int* __restrict__ src, const int* __restrict__ dst, int E) {
    int e = blockIdx.x * blockDim.x + threadIdx.x;
    int pred = (e < E) && (src[e] < dst[e]);
    unsigned bal = __ballot_sync(0xffffffffu, pred);
    __shared__ int wc[32];
    int wid = threadIdx.x >> 5, lane = threadIdx.x & 31;
    if (lane == 0) wc[wid] = __popc(bal);
    __syncthreads();
    if (threadIdx.x == 0) {
        int nmw = blockDim.x >> 5, s = 0;
        for (int i = 0; i < nmw; i++) s += wc[i];
        g_bcnt[blockIdx.x] = s;
    }
}
__global__ void k_scan(int nb) {
    __shared__ int s[1024];
    int t = threadIdx.x;
    if (t < nb) s[t] = g_bcnt[t];
    __syncthreads();
    if (t == 0) { int acc = 0; for (int i = 0; i < nb; i++) { int v = s[i]; s[i] = acc; acc += v; } }
    __syncthreads();
    if (t < nb) g_boff[t] = s[t];
}
__global__ void k_scatter(const int* __restrict__ src, const int* __restrict__ dst,
                          const float* __restrict__ ea, int E) {
    int e = blockIdx.x * blockDim.x + threadIdx.x;
    int pred = (e < E) && (src[e] < dst[e]);
    unsigned bal = __ballot_sync(0xffffffffu, pred);
    __shared__ int wc[32], ws[32];
    int wid = threadIdx.x >> 5, lane = threadIdx.x & 31;
    if (lane == 0) wc[wid] = __popc(bal);
    __syncthreads();
    if (threadIdx.x == 0) {
        int nmw = blockDim.x >> 5, acc = 0;
        for (int i = 0; i < nmw; i++) { ws[i] = acc; acc += wc[i]; }
    }
    __syncthreads();
    if (pred) {
        int idx = g_boff[blockIdx.x] + ws[wid] + __popc(bal & ((1u << lane) - 1u));
        g_ssrc[idx] = src[e];
        g_sdst[idx] = dst[e];
        #pragma unroll
        for (int k = 0; k < 6; k++) g_sea[idx * 6 + k] = ea[(size_t)e * 6 + k];
    }
}

// ============================ prep: coalesced transposes + misc ============================
__global__ __launch_bounds__(256)
void k_tw2(const float* __restrict__ W2) {
    __shared__ float tile[32][33];
    int bx = blockIdx.x * 32, by = blockIdx.y * 32;
    int tx = threadIdx.x & 31, ty = threadIdx.x >> 5;
    #pragma unroll
    for (int i = 0; i < 4; i++) {
        int k = by + ty + i * 8;
        tile[ty + i * 8][tx] = W2[(size_t)k * HID + bx + tx];
    }
    __syncthreads();
    #pragma unroll
    for (int i = 0; i < 4; i++) {
        int n = bx + ty + i * 8;
        g_w2t[(size_t)n * HID + by + tx] = __float2half_rn(tile[tx][ty + i * 8]);
    }
}
__global__ __launch_bounds__(256)
void k_tw3(const float* __restrict__ W3) {
    __shared__ float tile[32][33];
    int bx = blockIdx.x * 32, by = blockIdx.y * 32;
    int tx = threadIdx.x & 31, ty = threadIdx.x >> 5;
    #pragma unroll
    for (int i = 0; i < 4; i++) {
        int k = by + ty + i * 8;
        int n = bx + tx;
        tile[ty + i * 8][tx] = (n < MSG) ? W3[(size_t)k * MSG + n] : 0.f;
    }
    __syncthreads();
    #pragma unroll
    for (int i = 0; i < 4; i++) {
        int n = bx + ty + i * 8;
        g_w3t[(size_t)n * HID + by + tx] = __float2half_rn(tile[tx][ty + i * 8]);
    }
}
__global__ void k_misc(const float* __restrict__ b3) {
    int idx = blockIdx.x * blockDim.x + threadIdx.x;
    if (idx < MSGP) g_b3p[idx] = (idx < MSG) ? b3[idx] : 0.f;
    if (idx < NNODES * 3) g_agg[idx] = 0.f;
    if (idx == 0) {
        int p = 0;
        for (int a = 0; a < 6; a++) g_pidx[p++] = a | (6 << 8) | (6 << 16);
        for (int a = 0; a < 6; a++)
            for (int b = a; b < 6; b++) g_pidx[p++] = a | (b << 8) | (6 << 16);
        for (int a = 0; a < 6; a++)
            for (int b = a; b < 6; b++)
                for (int c = b; c < 6; c++) g_pidx[p++] = a | (b << 8) | (c << 16);
    }
}

// ============================ layer1 (R8-proven): [Esel,6]@[6,768], leaky, fp16 out ============================
#define L1_EPB 8
__global__ void k_layer1(const float* __restrict__ W1, const float* __restrict__ b1, int esel) {
    int e0 = blockIdx.x * L1_EPB;
    __shared__ float ea[L1_EPB][6];
    int t = threadIdx.x;
    if (t < L1_EPB * 6) ea[t / 6][t % 6] = g_sea[e0 * 6 + t];
    __syncthreads();
    for (int n = t; n < HID; n += blockDim.x) {
        float w[6];
        #pragma unroll
        for (int k = 0; k < 6; k++) w[k] = W1[k * HID + n];
        float bb = b1[n];
        #pragma unroll
        for (int e = 0; e < L1_EPB; e++) {
            float acc = bb;
            #pragma unroll
            for (int k = 0; k < 6; k++) acc += ea[e][k] * w[k];
            g_h1[(size_t)(e0 + e) * HID + n] = __float2half_rn(leaky(acc));
        }
    }
}

// ============================ GEMM2: warp-MMA single-fp16, forced 2 CTAs/SM ============================
#define GSTAGE    16384
#define GEMM_SMEM (4 * GSTAGE + 128)

__global__ __launch_bounds__(256, 2)
void k_gemm_mma(const __half* __restrict__ A, const __half* __restrict__ B,
                const float* __restrict__ bias, __half* __restrict__ Ch,
                int K, int ldc)
{
    extern __shared__ char smem[];
    uint32_t sbase = (smem_to_u32(smem) + 127) & ~127u;
    int tid = threadIdx.x;
    int wid = tid >> 5, lane = tid & 31;
    int wm = wid >> 2, wn = wid & 3;
    int m0 = blockIdx.y * 128, n0 = blockIdx.x * 128;
    int S = K / 32;

    float acc[16][4];
    #pragma unroll
    for (int i = 0; i < 16; i++)
        #pragma unroll
        for (int j = 0; j < 4; j++) acc[i][j] = 0.f;

    auto load_stage = [&](int s, int b) {
        uint32_t bo = sbase + (uint32_t)b * GSTAGE;
        #pragma unroll
        for (int t = 0; t < 4; t++) {
            int i   = tid + t * 256;
            int mat = i >> 9;
            int rem = i & 511;
            int row = rem >> 2;
            int c   = rem & 3;
            const __half* g = (mat == 0 ? A + (size_t)(m0 + row) * K
                                        : B + (size_t)(n0 + row) * K);
            g += s * 32 + c * 8;
            uint32_t dstr = bo + (uint32_t)mat * 8192 + (uint32_t)row * 64
                          + (uint32_t)((c ^ (row & 3)) << 4);
            cp16(dstr, g);
        }
    };

    uint32_t aOff[4], aR3[4], bOff[4], bR3[4];
    {
        int arow_base = wm * 64 + ((lane >> 3) & 1) * 8 + (lane & 7);
        #pragma unroll
        for (int mt = 0; mt < 4; mt++) {
            int r = arow_base + mt * 16;
            aOff[mt] = (uint32_t)r * 64;
            aR3[mt] = (uint32_t)(r & 3);
        }
        int brow_base = wn * 32 + (lane & 7);
        #pragma unroll
        for (int nt = 0; nt < 4; nt++) {
            int r = brow_base + nt * 8;
            bOff[nt] = 8192u + (uint32_t)r * 64;
            bR3[nt] = (uint32_t)(r & 3);
        }
    }
    uint32_t aKadd = (uint32_t)(lane >> 4);
    uint32_t bKadd = (uint32_t)((lane >> 3) & 1);

    auto compute = [&](int b) {
        uint32_t base = sbase + (uint32_t)b * GSTAGE;
        #pragma unroll
        for (int ks = 0; ks < 2; ks++) {
            uint32_t af[4][4], bf[4][2];
            #pragma unroll
            for (int mt = 0; mt < 4; mt++) {
                uint32_t c = (uint32_t)(ks * 2) + aKadd;
                ldsm_x4(af[mt], base + aOff[mt] + ((c ^ aR3[mt]) << 4));
            }
            #pragma unroll
            for (int nt = 0; nt < 4; nt++) {
                uint32_t c = (uint32_t)(ks * 2) + bKadd;
                ldsm_x2(bf[nt], base + bOff[nt] + ((c ^ bR3[nt]) << 4));
            }
            #pragma unroll
            for (int mt = 0; mt < 4; mt++)
                #pragma unroll
                for (int nt = 0; nt < 4; nt++)
                    mma16816(acc[mt * 4 + nt], af[mt], bf[nt]);
        }
    };

    load_stage(0, 0); CP_COMMIT;
    load_stage(1, 1); CP_COMMIT;
    load_stage(2, 2); CP_COMMIT;
    for (int s = 0; s < S; s++) {
        CP_WAIT2;
        __syncthreads();
        if (s + 3 < S) load_stage(s + 3, (s + 3) & 3);
        CP_COMMIT;
        compute(s & 3);
    }

    int r0 = m0 + wm * 64 + (lane >> 2);
    int c0 = n0 + wn * 32 + 2 * (lane & 3);
    #pragma unroll
    for (int mt = 0; mt < 4; mt++) {
        #pragma unroll
        for (int nt = 0; nt < 4; nt++) {
            int row = r0 + mt * 16;
            int col = c0 + nt * 8;
            const float* a = acc[mt * 4 + nt];
            float b0 = bias[col], b1v = bias[col + 1];
            __half2 hh0, hh1;
            hh0.x = __float2half_rn(leaky(a[0] + b0));
            hh0.y = __float2half_rn(leaky(a[1] + b1v));
            hh1.x = __float2half_rn(leaky(a[2] + b0));
            hh1.y = __float2half_rn(leaky(a[3] + b1v));
            *(__half2*)(Ch + (size_t)row * ldc + col) = hh0;
            *(__half2*)(Ch + (size_t)(row + 8) * ldc + col) = hh1;
        }
    }
}

// ============================ GEMM3 (N=256) + fused einsum/scatter (R8-proven, exact) ============================
#define G3_STAGE 24576
#define G3_SPROD (4 * G3_STAGE)
#define G3_SEA   (G3_SPROD + 128 * 84 * 4)
#define G3_SRES  (G3_SEA + 128 * 8 * 4)
#define G3_SB3   (G3_SRES + 128 * 4 * 4)
#define G3_SMEM  (G3_SB3 + 256 * 4 + 256)

__global__ __launch_bounds__(512, 1)
void k_gemm3m(const __half* __restrict__ A, const __half* __restrict__ B)
{
    extern __shared__ char smem[];
    char* smc = (char*)(((uintptr_t)smem + 127) & ~(uintptr_t)127);
    uint32_t sbase = smem_to_u32(smc);
    float* sprod = (float*)(smc + G3_SPROD);
    float* sea   = (float*)(smc + G3_SEA);
    float* sres  = (float*)(smc + G3_SRES);
    float* sb3   = (float*)(smc + G3_SB3);
    int tid = threadIdx.x;
    int wid = tid >> 5, lane = tid & 31;
    int wm = wid >> 2, wn = wid & 3;
    int m0 = blockIdx.x * 128;
    const int S = HID / 32;

    float acc[16][4];
    #pragma unroll
    for (int i = 0; i < 16; i++)
        #pragma unroll
        for (int j = 0; j < 4; j++) acc[i][j] = 0.f;

    auto load_stage = [&](int s, int b) {
        uint32_t bo = sbase + (uint32_t)b * G3_STAGE;
        #pragma unroll
        for (int t = 0; t < 3; t++) {
            int i = tid + t * 512;
            if (i < 512) {
                int row = i >> 2, c = i & 3;
                cp16(bo + (uint32_t)row * 64 + (uint32_t)((c ^ (row & 3)) << 4),
                     A + (size_t)(m0 + row) * HID + s * 32 + c * 8);
            } else {
                int j = i - 512;
                int row = j >> 2, c = j & 3;
                cp16(bo + 8192u + (uint32_t)row * 64 + (uint32_t)((c ^ (row & 3)) << 4),
                     B + (size_t)row * HID + s * 32 + c * 8);
            }
        }
    };

    load_stage(0, 0); CP_COMMIT;
    load_stage(1, 1); CP_COMMIT;
    load_stage(2, 2); CP_COMMIT;

    for (int i = tid; i < 768; i += 512) {
        int r = i / 6, k = i - r * 6;
        sea[r * 8 + k] = g_sea[(size_t)(m0 + r) * 6 + k];
    }
    if (tid < 128) { sea[tid * 8 + 6] = 1.f; sea[tid * 8 + 7] = 1.f; }
    for (int i = tid; i < 256; i += 512) sb3[i] = g_b3p[i];
    if (tid < 512) sres[tid] = 0.f;
    __syncthreads();
    for (int i = tid; i < 128 * 83; i += 512) {
        int e = i / 83, p = i - e * 83;
        int pk = g_pidx[p];
        sprod[e * 84 + p] = sea[e * 8 + (pk & 255)] * sea[e * 8 + ((pk >> 8) & 255)]
                          * sea[e * 8 + ((pk >> 16) & 255)];
    }

    uint32_t aOff[2], aR3[2], bOff[8], bR3[8];
    {
        int arow_base = wm * 32 + ((lane >> 3) & 1) * 8 + (lane & 7);
        #pragma unroll
        for (int mt = 0; mt < 2; mt++) {
            int r = arow_base + mt * 16;
            aOff[mt] = (uint32_t)r * 64;
            aR3[mt] = (uint32_t)(r & 3);
        }
        int brow_base = wn * 64 + (lane & 7);
        #pragma unroll
        for (int nt = 0; nt < 8; nt++) {
            int r = brow_base + nt * 8;
            bOff[nt] = 8192u + (uint32_t)r * 64;
            bR3[nt] = (uint32_t)(r & 3);
        }
    }
    uint32_t aKadd = (uint32_t)(lane >> 4);
    uint32_t bKadd = (uint32_t)((lane >> 3) & 1);

    auto compute = [&](int b) {
        uint32_t base = sbase + (uint32_t)b * G3_STAGE;
        #pragma unroll
        for (int ks = 0; ks < 2; ks++) {
            uint32_t af[2][4], bf[8][2];
            #pragma unroll
            for (int mt = 0; mt < 2; mt++) {
                uint32_t c = (uint32_t)(ks * 2) + aKadd;
                ldsm_x4(af[mt], base + aOff[mt] + ((c ^ aR3[mt]) << 4));
            }
            #pragma unroll
            for (int nt = 0; nt < 8; nt++) {
                uint32_t c = (uint32_t)(ks * 2) + bKadd;
                ldsm_x2(bf[nt], base + bOff[nt] + ((c ^ bR3[nt]) << 4));
            }
            #pragma unroll
            for (int mt = 0; mt < 2; mt++)
                #pragma unroll
                for (int nt = 0; nt < 8; nt++)
                    mma16816(acc[mt * 8 + nt], af[mt], bf[nt]);
        }
    };

    for (int s = 0; s < S; s++) {
        CP_WAIT2;
        __syncthreads();
        if (s + 3 < S) load_stage(s + 3, (s + 3) & 3);
        CP_COMMIT;
        compute(s & 3);
    }
    __syncthreads();

    int lr = lane >> 2;
    int lc2 = 2 * (lane & 3);
    #pragma unroll
    for (int mt = 0; mt < 2; mt++) {
        int row0 = wm * 32 + mt * 16 + lr;
        int row1 = row0 + 8;
        float p0[3] = {0.f, 0.f, 0.f}, p1[3] = {0.f, 0.f, 0.f};
        #pragma unroll
        for (int nt = 0; nt < 8; nt++) {
            const float* a = acc[mt * 8 + nt];
            int colb = wn * 64 + nt * 8 + lc2;
            #pragma unroll
            for (int q = 0; q < 2; q++) {
                int j = colb + q;
                if (j < MSG) {
                    int k = j / 83;
                    int p = j - k * 83;
                    float w0 = a[q]     + sb3[j];
                    float w1 = a[2 + q] + sb3[j];
                    p0[k] += w0 * sprod[row0 * 84 + p];
                    p1[k] += w1 * sprod[row1 * 84 + p];
                }
            }
        }
        #pragma unroll
        for (int k = 0; k < 3; k++) {
            atomicAdd(&sres[row0 * 4 + k], p0[k]);
            atomicAdd(&sres[row1 * 4 + k], p1[k]);
        }
    }
    __syncthreads();

    if (tid < 128) {
        int e = m0 + tid;
        int s = g_ssrc[e], d = g_sdst[e];
        float r0 = sres[tid * 4 + 0], r1 = sres[tid * 4 + 1], r2 = sres[tid * 4 + 2];
        atomicAdd(&g_agg[d * 3 + 0],  r0);
        atomicAdd(&g_agg[d * 3 + 1],  r1);
        atomicAdd(&g_agg[d * 3 + 2],  r2);
        atomicAdd(&g_agg[s * 3 + 0], -r0);
        atomicAdd(&g_agg[s * 3 + 1], -r1);
        atomicAdd(&g_agg[s * 3 + 2], -r2);
    }
}

// ============================ node update: LN(19)+MLP ============================
__global__ void k_update(const float* __restrict__ x,
                         const float* __restrict__ ln_g, const float* __restrict__ ln_b,
                         const float* __restrict__ uW1, const float* __restrict__ ub1,
                         const float* __restrict__ uW2, const float* __restrict__ ub2,
                         const float* __restrict__ uW3, const float* __restrict__ ub3,
                         float* __restrict__ out) {
    __shared__ float sW1[19 * 18], sW2[18 * 17], sW3[17 * 16];
    __shared__ float sb1[18], sb2[17], sb3[16], sg[19], sbt[19];
    int t = threadIdx.x;
    for (int i = t; i < 19 * 18; i += blockDim.x) sW1[i] = uW1[i];
    for (int i = t; i < 18 * 17; i += blockDim.x) sW2[i] = uW2[i];
    for (int i = t; i < 17 * 16; i += blockDim.x) sW3[i] = uW3[i];
    if (t < 18) sb1[t] = ub1[t];
    if (t < 17) sb2[t] = ub2[t];
    if (t < 16) sb3[t] = ub3[t];
    if (t < 19) { sg[t] = ln_g[t]; sbt[t] = ln_b[t]; }
    __syncthreads();

    int node = blockIdx.x * blockDim.x + t;
    if (node >= NNODES) return;

    float h[19];
    #pragma unroll
    for (int i = 0; i < 16; i++) h[i] = x[node * 16 + i];
    #pragma unroll
    for (int k = 0; k < 3; k++) h[16 + k] = g_agg[node * 3 + k];

    float mu = 0.f;
    #pragma unroll
    for (int i = 0; i < 19; i++) mu += h[i];
    mu *= (1.f / 19.f);
    float var = 0.f;
    #pragma unroll
    for (int i = 0; i < 19; i++) { float dlt = h[i] - mu; var += dlt * dlt; }
    var *= (1.f / 19.f);
    float rs = rsqrtf(var + LN_EPS);
    float hn[19];
    #pragma unroll
    for (int i = 0; i < 19; i++) hn[i] = (h[i] - mu) * rs * sg[i] + sbt[i];

    float t1[18];
    #pragma unroll
    for (int j = 0; j < 18; j++) {
        float acc = sb1[j];
        #pragma unroll
        for (int i = 0; i < 19; i++) acc += hn[i] * sW1[i * 18 + j];
        t1[j] = leaky(acc);
    }
    float t2[17];
    #pragma unroll
    for (int j = 0; j < 17; j++) {
        float acc = sb2[j];
        #pragma unroll
        for (int i = 0; i < 18; i++) acc += t1[i] * sW2[i * 17 + j];
        t2[j] = leaky(acc);
    }
    #pragma unroll
    for (int j = 0; j < 16; j++) {
        float acc = sb3[j];
        #pragma unroll
        for (int i = 0; i < 17; i++) acc += t2[i] * sW3[i * 16 + j];
        out[node * 16 + j] = acc;
    }
}

// ============================ launch ============================
extern "C" void kernel_launch(void* const* d_in, const int* in_sizes, int n_in,
                              void* d_out, int out_size) {
    const float* x    = (const float*)d_in[0];
    const float* ea   = (const float*)d_in[1];
    const float* mW1  = (const float*)d_in[2];
    const float* mb1  = (const float*)d_in[3];
    const float* mW2  = (const float*)d_in[4];
    const float* mb2  = (const float*)d_in[5];
    const float* mW3  = (const float*)d_in[6];
    const float* mb3  = (const float*)d_in[7];
    const float* ln_g = (const float*)d_in[8];
    const float* ln_b = (const float*)d_in[9];
    const float* uW1  = (const float*)d_in[10];
    const float* ub1  = (const float*)d_in[11];
    const float* uW2  = (const float*)d_in[12];
    const float* ub2  = (const float*)d_in[13];
    const float* uW3  = (const float*)d_in[14];
    const float* ub3  = (const float*)d_in[15];
    const int*   eidx = (const int*)d_in[16];

    int E = in_sizes[1] / 6;               // 131072
    const int* src = eidx;
    const int* dst = eidx + E;
    int esel = E / 2;                      // 65536
    int NB = (E + 1023) / 1024;

    __half *p_h1, *p_h2, *p_w2t, *p_w3t;
    cudaGetSymbolAddress((void**)&p_h1,  g_h1);
    cudaGetSymbolAddress((void**)&p_h2,  g_h2);
    cudaGetSymbolAddress((void**)&p_w2t, g_w2t);
    cudaGetSymbolAddress((void**)&p_w3t, g_w3t);

    cudaFuncSetAttribute(k_gemm_mma, cudaFuncAttributeMaxDynamicSharedMemorySize, GEMM_SMEM);
    cudaFuncSetAttribute(k_gemm3m,  cudaFuncAttributeMaxDynamicSharedMemorySize, G3_SMEM);

    k_misc   <<<(NNODES * 3 + 255) / 256, 256>>>(mb3);
    {
        dim3 bt(256); dim3 gt2(HID / 32, HID / 32);
        k_tw2<<<gt2, bt>>>(mW2);
        dim3 gt3(MSGP / 32, HID / 32);
        k_tw3<<<gt3, bt>>>(mW3);
    }
    k_count  <<<NB, 1024>>>(src, dst, E);
    k_scan   <<<1, 1024>>>(NB);
    k_scatter<<<NB, 1024>>>(src, dst, ea, E);

    k_layer1 <<<esel / L1_EPB, 256>>>(mW1, mb1, esel);

    // GEMM2: h2 = leaky(h1 @ W2 + b2), fp16 out, 2 CTAs/SM forced
    dim3 g2(HID / 128, esel / 128);
    k_gemm_mma<<<g2, 256, GEMM_SMEM>>>(p_h1, p_w2t, mb2, p_h2, HID, HID);

    // GEMM3 + einsum + antisymmetric scatter
    k_gemm3m<<<esel / 128, 512, G3_SMEM>>>(p_h2, p_w3t);

    k_update<<<(NNODES + 127) / 128, 128>>>(x, ln_g, ln_b, uW1, ub1, uW2, ub2,
                                            uW3, ub3, (float*)d_out);
}